// round 15
// baseline (speedup 1.0000x reference)
#include <cuda_runtime.h>
#include <cstdint>

#define BATCH  64
#define NRES   4096
#define NROWS  4128                     // 4096 reservoir + 10 classifier + 22 pad
#define TSTEPS 128
#define NCLS   10

#define MTILE  32
#define NTILES (NROWS / MTILE)          // 129
#define TOTCH  (NTILES * 16)            // 2064 chunk-items (16 x k256 per tile)
#define NCTA   152                      // GB300 SM count: one CTA per SM
#define NLIMB  4
#define SCALE  8589934592.0             // 2^33 (proven exact-enough)
#define INVSCALE (1.0 / 8589934592.0)

#define KTILES  (NRES / 128)            // 32 global 128-k tiles
#define ATILE_B 4096                    // swizzled 32x128 s8 tile
#define BTILE_B 8192                    // swizzled 64x128 s8 tile
#define SSZ     (KTILES * BTILE_B)      // one spike buffer: 256 KB

#define NSTAGE   3
#define SM_ABYTES (NLIMB * 2 * ATILE_B) // 32768: 4 limbs x 2 k-tiles
#define SM_BUF    (SM_ABYTES + 2 * BTILE_B)  // 49152
#define SM_DATA   (NSTAGE * SM_BUF)          // 147456
#define SM_TOTAL  (SM_DATA + 64)

// ---------------- device scratch (no runtime allocation) ----------------
__device__ __align__(16384) int8_t g_Lsw[NLIMB][(size_t)NROWS * NRES];  // 32-row swizzled limb tiles
__device__ __align__(16384) int8_t g_S[2][SSZ];                         // spikes, double buffered
__device__ long long g_acc[(size_t)NTILES * 2048];  // per-tile int64 partial sums [tile][nloc][b]
__device__ int       g_cnt[NTILES];                 // per-tile arrived-chunk counters
__device__ float g_vr[NRES * BATCH];    // [n][b]
__device__ float g_vc[BATCH * NCLS];

// ---------------- helpers ----------------
__device__ __forceinline__ uint32_t smem_u32(const void* p) {
    uint32_t a;
    asm("{ .reg .u64 t; cvta.to.shared.u64 t, %1; cvt.u32.u64 %0, t; }" : "=r"(a) : "l"(p));
    return a;
}
#define SWZ(off) ((off) ^ (((off) >> 3) & 0x70))

#define MBARRIER_INIT(mb, cnt) \
    asm volatile("mbarrier.init.shared.b64 [%0], %1;" :: "r"((uint32_t)(mb)), "r"((uint32_t)(cnt)) : "memory")
#define MBARRIER_EXPECT_TX(mb, bytes) \
    asm volatile("mbarrier.arrive.expect_tx.shared.b64 _, [%0], %1;" \
                 :: "r"((uint32_t)(mb)), "r"((uint32_t)(bytes)) : "memory")
#define MBARRIER_WAIT_PARITY(mb, par) do {                                   \
    uint32_t _m = (uint32_t)(mb), _p = (uint32_t)(par);                      \
    asm volatile(                                                            \
        "{\n\t.reg .pred P1;\n\t"                                            \
        "WL_%=:\n\t"                                                         \
        "mbarrier.try_wait.parity.acquire.cta.shared::cta.b64 P1, [%0], %1, 0x989680;\n\t" \
        "@P1 bra.uni WD_%=;\n\t"                                             \
        "bra.uni WL_%=;\n\t"                                                 \
        "WD_%=:\n\t}"                                                        \
        :: "r"(_m), "r"(_p) : "memory");                                     \
} while (0)

__device__ __forceinline__ void bulk_cp(uint32_t dst, const void* src, uint32_t bytes, uint32_t mbar) {
    asm volatile(
        "cp.async.bulk.shared::cluster.global.mbarrier::complete_tx::bytes [%0], [%1], %2, [%3];"
        :: "r"(dst), "l"(src), "r"(bytes), "r"(mbar) : "memory");
}
__device__ __forceinline__ void ldmx4(uint32_t* r, uint32_t a) {
    asm volatile("ldmatrix.sync.aligned.m8n8.x4.shared.b16 {%0,%1,%2,%3}, [%4];"
                 : "=r"(r[0]), "=r"(r[1]), "=r"(r[2]), "=r"(r[3]) : "r"(a));
}
__device__ __forceinline__ void ldmx2(uint32_t* r, uint32_t a) {
    asm volatile("ldmatrix.sync.aligned.m8n8.x2.shared.b16 {%0,%1}, [%2];"
                 : "=r"(r[0]), "=r"(r[1]) : "r"(a));
}
__device__ __forceinline__ void imma16832(int* d, const uint32_t* a, const uint32_t* b) {
    asm volatile(
        "mma.sync.aligned.m16n8k32.row.col.s32.s8.s8.s32 "
        "{%0,%1,%2,%3}, {%4,%5,%6,%7}, {%8,%9}, {%0,%1,%2,%3};"
        : "+r"(d[0]), "+r"(d[1]), "+r"(d[2]), "+r"(d[3])
        : "r"(a[0]), "r"(a[1]), "r"(a[2]), "r"(a[3]), "r"(b[0]), "r"(b[1]));
}

// ---------------------------------------------------------------------------
// Once per replay: v = round(w*2^33) -> 4 balanced radix-256 digits, stored
// pre-swizzled in 32-row tile-contiguous layout. Rows: [W_res ; W_out ; 0].
// ---------------------------------------------------------------------------
__global__ __launch_bounds__(256) void split_w(const float* __restrict__ Wres,
                                               const float* __restrict__ Wout) {
    size_t i = (size_t)blockIdx.x * 256 + threadIdx.x;  // i = n*4096 + k over NROWS*NRES
    int n = (int)(i >> 12), k = (int)(i & 4095);
    float w = 0.0f;
    if (n < NRES)             w = Wres[i];
    else if (n < NRES + NCLS) w = Wout[(size_t)(n - NRES) * NRES + k];
    long long v = __double2ll_rn((double)w * SCALE);
    size_t tile  = ((size_t)(n >> 5) * KTILES + (k >> 7)) * ATILE_B;
    size_t inner = SWZ((uint32_t)((n & 31) * 128 + (k & 127)));
#pragma unroll
    for (int j = 0; j < NLIMB; j++) {
        long long d = ((v + 128) & 255) - 128;
        g_Lsw[j][tile + inner] = (int8_t)d;
        v = (v - d) >> 8;
    }
}

__global__ __launch_bounds__(256) void init_state(float* __restrict__ out) {
    int i = blockIdx.x * 256 + threadIdx.x;        // grid covers NTILES*2048 = 264192
    if (i < NTILES * 2048) g_acc[i] = 0;
    if (i < NTILES)        g_cnt[i] = 0;
    if (i < SSZ)           g_S[0][i] = 0;          // S(-1) = 0 (buffer 0)
    if (i < NRES * BATCH)  g_vr[i] = 0.0f;
    if (i < BATCH * NCLS) {
        g_vc[i] = 0.0f;
        out[i]  = 0.0f;
    }
}

// no-op node: keeps the ncu-captured launch position on step_mma
__global__ void pad_kernel() {}

// ---------------------------------------------------------------------------
// step_mma (balanced + fused): 2064 chunk-items statically partitioned over
// 152 CTAs (max 14 chunks/CTA vs 16 before). Each CTA accumulates exact int64
// partials per tile, flushes via atomicAdd (order-free, deterministic), and
// the CTA whose counter-add completes a tile's 16 chunks runs that tile's
// LIF epilogue at kernel end (threadFenceReduction idiom), resetting
// g_acc/g_cnt for the next step.
// ---------------------------------------------------------------------------
__global__ __launch_bounds__(256, 1) void step_mma(const float* __restrict__ x,
                                                   const float* __restrict__ W_in,
                                                   float* __restrict__ out, int t) {
    extern __shared__ __align__(1024) char smem[];
    __shared__ int sm_fin;
    const uint32_t sbase = smem_u32(smem);
    const uint32_t mbar0 = sbase + SM_DATA;
    const int tid  = threadIdx.x;
    const int lane = tid & 31;
    const int warp = tid >> 5;
    const int wm   = warp & 1;           // 0..1 (M, 16 rows)
    const int wn   = warp >> 1;          // 0..3 (N, 16 cols)
    const int bid  = blockIdx.x;

    const int g_lo = (TOTCH * bid) / NCTA;
    const int g_hi = (TOTCH * (bid + 1)) / NCTA;   // 13 or 14 chunks

    const int8_t* __restrict__ Ssrc = g_S[t & 1];
    int8_t* __restrict__       Sdst = g_S[(t + 1) & 1];

    if (tid == 0) {
#pragma unroll
        for (int s = 0; s < NSTAGE; s++) MBARRIER_INIT(mbar0 + 8 * s, 1);
    }
    __syncthreads();

    auto issue = [&](int gg, int buf) {
        const int mt  = gg >> 4;
        const int kt0 = (gg & 15) * 2;               // first 128-k tile of chunk
        const uint32_t st = sbase + buf * SM_BUF;
        const uint32_t mb = mbar0 + 8 * buf;
        MBARRIER_EXPECT_TX(mb, SM_BUF);
#pragma unroll
        for (int li = 0; li < NLIMB; li++)
            bulk_cp(st + li * (2 * ATILE_B),
                    g_Lsw[li] + ((size_t)mt * KTILES + kt0) * ATILE_B,
                    2 * ATILE_B, mb);
        bulk_cp(st + SM_ABYTES, Ssrc + (size_t)kt0 * BTILE_B, 2 * BTILE_B, mb);
    };

    if (tid == 0) { issue(g_lo, 0); issue(g_lo + 1, 1); issue(g_lo + 2, 2); }

    long long tt[2][4];
#pragma unroll
    for (int ni = 0; ni < 2; ni++)
#pragma unroll
        for (int j = 0; j < 4; j++) tt[ni][j] = 0;

    const int arow  = wm * 16 + (lane & 15);
    const int acolx = (lane >> 4) << 4;
    const int brow  = wn * 16 + (lane & 7);
    const int bcolx = ((lane >> 3) & 1) << 4;
    const int gl = lane >> 2, t4 = lane & 3;

    int cbuf = 0, cpar = 0, pbuf = 0;
    int nch = 0;
    int fin[2]; int nfin = 0;

    for (int g = g_lo; g < g_hi; g++) {
        MBARRIER_WAIT_PARITY(mbar0 + 8 * cbuf, cpar);

        const uint32_t abase = sbase + cbuf * SM_BUF;
        const uint32_t bbase = abase + SM_ABYTES;

        int acc[NLIMB][2][4];
#pragma unroll
        for (int li = 0; li < NLIMB; li++)
#pragma unroll
            for (int ni = 0; ni < 2; ni++)
#pragma unroll
                for (int j = 0; j < 4; j++) acc[li][ni][j] = 0;

#pragma unroll
        for (int kk = 0; kk < 8; kk++) {             // 8 x k32 per 256-k chunk
            const uint32_t asub0 = abase + (kk >> 2) * ATILE_B;
            const uint32_t bsub  = bbase + (kk >> 2) * BTILE_B;
            const int kko = (kk & 3) * 32;
            uint32_t b[2][2];
#pragma unroll
            for (int ni = 0; ni < 2; ni++)
                ldmx2(b[ni], bsub + SWZ((brow + ni * 8) * 128 + kko + bcolx));
#pragma unroll
            for (int li = 0; li < NLIMB; li++) {
                uint32_t a[4];
                ldmx4(a, asub0 + li * (2 * ATILE_B) + SWZ(arow * 128 + kko + acolx));
#pragma unroll
                for (int ni = 0; ni < 2; ni++)
                    imma16832(acc[li][ni], a, b[ni]);
            }
        }
#pragma unroll
        for (int li = 0; li < NLIMB; li++)
#pragma unroll
            for (int ni = 0; ni < 2; ni++)
#pragma unroll
                for (int j = 0; j < 4; j++)
                    tt[ni][j] += ((long long)acc[li][ni][j]) << (8 * li);
        nch++;

        __syncthreads();                             // smem buffer reuse safety
        if (tid == 0 && g + 3 < g_hi) issue(g + 3, pbuf);
        if (++pbuf == NSTAGE) pbuf = 0;
        if (++cbuf == NSTAGE) { cbuf = 0; cpar ^= 1; }

        // tile boundary (or range end): flush exact partials
        if (((g & 15) == 15) || (g + 1 == g_hi)) {
            const int mt = g >> 4;
            unsigned long long* base = (unsigned long long*)(g_acc + (size_t)mt * 2048);
#pragma unroll
            for (int ni = 0; ni < 2; ni++)
#pragma unroll
                for (int h = 0; h < 2; h++)
#pragma unroll
                    for (int q = 0; q < 2; q++) {
                        int nloc = wm * 16 + gl + h * 8;
                        int b    = wn * 16 + ni * 8 + t4 * 2 + q;
                        atomicAdd(&base[nloc * 64 + b],
                                  (unsigned long long)tt[ni][h * 2 + q]);
                        tt[ni][h * 2 + q] = 0;
                    }
            __threadfence();
            __syncthreads();                         // all atomics + fences done
            if (tid == 0) {
                int old = atomicAdd(&g_cnt[mt], nch);
                sm_fin = (old + nch == 16) ? 1 : 0;
            }
            __syncthreads();
            if (sm_fin) fin[nfin++] = mt;
            nch = 0;
        }
    }

    // ---- LIF epilogue for tiles this CTA finished (0..2 tiles) ----
    for (int f = 0; f < nfin; f++) {
        const int mtf = fin[f], m0f = mtf * MTILE;
        long long* base = g_acc + (size_t)mtf * 2048;
        for (int e = tid; e < 2048; e += 256) {
            int nloc = e >> 6, b = e & 63;
            int n = m0f + nloc;
            long long T = base[e];
            base[e] = 0;                             // reset for next step
            float dotf = (float)((double)T * INVSCALE);
            if (n < NRES) {
                int   idx = n * BATCH + b;
                float xw  = __fmul_rn(x[b * TSTEPS + t], W_in[n]);
                float cur = __fadd_rn(xw, dotf);
                float v   = __fadd_rn(__fmul_rn(0.9f, g_vr[idx]), cur);
                float s   = (v >= 1.0f) ? 1.0f : 0.0f;
                g_vr[idx] = v * (1.0f - s);
                Sdst[(size_t)(n >> 7) * BTILE_B + SWZ((uint32_t)(b * 128 + (n & 127)))] = (int8_t)s;
            } else if (n < NRES + NCLS) {            // classifier, step t-1
                int   idx = b * NCLS + (n - NRES);
                float v   = __fadd_rn(__fmul_rn(0.9f, g_vc[idx]), dotf);
                float sc  = (v >= 1.0f) ? 1.0f : 0.0f;
                g_vc[idx] = v * (1.0f - sc);
                out[idx] += sc;
            }
        }
        if (tid == 0) g_cnt[mtf] = 0;                // reset counter for next step
    }
}

// ---------------------------------------------------------------------------
// final_readout: classifier update for the LAST step using S(T-1), fp64 dots.
// ---------------------------------------------------------------------------
__global__ __launch_bounds__(256) void final_readout(const float* __restrict__ W_out,
                                                     float* __restrict__ out) {
    __shared__ double red[8][NCLS];
    const int b = blockIdx.x, tid = threadIdx.x;
    const int k0 = tid * 16;

    float s[16];
    const int8_t* S = g_S[TSTEPS & 1] + (size_t)(k0 >> 7) * BTILE_B
                    + SWZ((uint32_t)(b * 128 + (k0 & 127)));
#pragma unroll
    for (int j = 0; j < 16; j++) s[j] = (float)S[j];

    double acc[NCLS];
#pragma unroll
    for (int c = 0; c < NCLS; c++) {
        const float* W = W_out + (size_t)c * NRES + k0;
        double a = 0.0;
#pragma unroll
        for (int j = 0; j < 16; j++) a += (double)s[j] * (double)W[j];
        acc[c] = a;
    }
#pragma unroll
    for (int c = 0; c < NCLS; c++)
#pragma unroll
        for (int o = 16; o > 0; o >>= 1)
            acc[c] += __shfl_down_sync(0xffffffff, acc[c], o);
    if ((tid & 31) == 0)
#pragma unroll
        for (int c = 0; c < NCLS; c++) red[tid >> 5][c] = acc[c];
    __syncthreads();

    if (tid < NCLS) {
        double dot = 0.0;
#pragma unroll
        for (int w = 0; w < 8; w++) dot += red[w][tid];
        int   idx = b * NCLS + tid;
        float v   = __fadd_rn(__fmul_rn(0.9f, g_vc[idx]), (float)dot);
        float sc  = (v >= 1.0f) ? 1.0f : 0.0f;
        g_vc[idx] = v * (1.0f - sc);
        out[idx] += sc;
    }
}

// ---------------------------------------------------------------------------
extern "C" void kernel_launch(void* const* d_in, const int* in_sizes, int n_in,
                              void* d_out, int out_size)
{
    const float* x     = (const float*)d_in[0];  // [64,1,128]
    const float* W_in  = (const float*)d_in[1];  // [4096,1]
    const float* W_res = (const float*)d_in[2];  // [4096,4096]
    const float* W_out = (const float*)d_in[3];  // [10,4096]
    float*       out   = (float*)d_out;          // [64,10]

    cudaFuncSetAttribute(step_mma, cudaFuncAttributeMaxDynamicSharedMemorySize, SM_TOTAL);

    split_w<<<((size_t)NROWS * NRES) / 256, 256>>>(W_res, W_out);
    init_state<<<(NTILES * 2048 + 255) / 256, 256>>>(out);
    pad_kernel<<<1, 32>>>();

    for (int t = 0; t < TSTEPS; t++)
        step_mma<<<NCTA, 256, SM_TOTAL>>>(x, W_in, out, t);

    final_readout<<<BATCH, 256>>>(W_out, out);   // classifier step T-1 with S(T-1)
}

// round 16
// speedup vs baseline: 1.1252x; 1.1252x over previous
#include <cuda_runtime.h>
#include <cstdint>

#define BATCH  64
#define NRES   4096
#define NROWS  4128                     // 4096 reservoir + 10 classifier + 22 pad
#define TSTEPS 128
#define NCLS   10

#define MTILE  32
#define MTILES (NROWS / MTILE)          // 129
#define NLIMB  4
#define NKCH   16                       // k-chunks of 256 over K=4096
#define SCALE  8589934592.0             // 2^33 (proven exact-enough)
#define INVSCALE (1.0 / 8589934592.0)

#define KTILES  (NRES / 128)            // 32 global 128-k tiles
#define ATILE_B 4096                    // swizzled 32x128 s8 tile
#define BTILE_B 8192                    // swizzled 64x128 s8 tile
#define SSZ     (KTILES * BTILE_B)      // one spike buffer: 256 KB

#define NSTAGE   3
#define SM_ABYTES (NLIMB * 2 * ATILE_B) // 32768: 4 limbs x 2 k-tiles
#define SM_BUF    (SM_ABYTES + 2 * BTILE_B)  // 49152
#define SM_DATA   (NSTAGE * SM_BUF)          // 147456
#define SM_D0     SM_DATA                    // int32 sD0[2048] = 8192 B
#define SM_MBAR   (SM_DATA + 8192)
#define SM_TOTAL  (SM_MBAR + 64)

#define THREADS 384                     // warps 0-7: IMMA (limbs 1-3); 8-11: dp4a (limb 0)

// ---------------- device scratch (no runtime allocation) ----------------
__device__ __align__(16384) int8_t g_Lsw[NLIMB][(size_t)NROWS * NRES];  // 32-row swizzled limb tiles
__device__ __align__(16384) int8_t g_S[2][SSZ];                         // spikes, double buffered
__device__ float g_vr[NRES * BATCH];    // [n][b]
__device__ float g_vc[BATCH * NCLS];

// ---------------- helpers ----------------
__device__ __forceinline__ uint32_t smem_u32(const void* p) {
    uint32_t a;
    asm("{ .reg .u64 t; cvta.to.shared.u64 t, %1; cvt.u32.u64 %0, t; }" : "=r"(a) : "l"(p));
    return a;
}
#define SWZ(off) ((off) ^ (((off) >> 3) & 0x70))

#define MBARRIER_INIT(mb, cnt) \
    asm volatile("mbarrier.init.shared.b64 [%0], %1;" :: "r"((uint32_t)(mb)), "r"((uint32_t)(cnt)) : "memory")
#define MBARRIER_EXPECT_TX(mb, bytes) \
    asm volatile("mbarrier.arrive.expect_tx.shared.b64 _, [%0], %1;" \
                 :: "r"((uint32_t)(mb)), "r"((uint32_t)(bytes)) : "memory")
#define MBARRIER_WAIT_PARITY(mb, par) do {                                   \
    uint32_t _m = (uint32_t)(mb), _p = (uint32_t)(par);                      \
    asm volatile(                                                            \
        "{\n\t.reg .pred P1;\n\t"                                            \
        "WL_%=:\n\t"                                                         \
        "mbarrier.try_wait.parity.acquire.cta.shared::cta.b64 P1, [%0], %1, 0x989680;\n\t" \
        "@P1 bra.uni WD_%=;\n\t"                                             \
        "bra.uni WL_%=;\n\t"                                                 \
        "WD_%=:\n\t}"                                                        \
        :: "r"(_m), "r"(_p) : "memory");                                     \
} while (0)

__device__ __forceinline__ void bulk_cp(uint32_t dst, const void* src, uint32_t bytes, uint32_t mbar) {
    asm volatile(
        "cp.async.bulk.shared::cluster.global.mbarrier::complete_tx::bytes [%0], [%1], %2, [%3];"
        :: "r"(dst), "l"(src), "r"(bytes), "r"(mbar) : "memory");
}
__device__ __forceinline__ void ldmx4(uint32_t* r, uint32_t a) {
    asm volatile("ldmatrix.sync.aligned.m8n8.x4.shared.b16 {%0,%1,%2,%3}, [%4];"
                 : "=r"(r[0]), "=r"(r[1]), "=r"(r[2]), "=r"(r[3]) : "r"(a));
}
__device__ __forceinline__ void ldmx2(uint32_t* r, uint32_t a) {
    asm volatile("ldmatrix.sync.aligned.m8n8.x2.shared.b16 {%0,%1}, [%2];"
                 : "=r"(r[0]), "=r"(r[1]) : "r"(a));
}
__device__ __forceinline__ void imma16832(int* d, const uint32_t* a, const uint32_t* b) {
    asm volatile(
        "mma.sync.aligned.m16n8k32.row.col.s32.s8.s8.s32 "
        "{%0,%1,%2,%3}, {%4,%5,%6,%7}, {%8,%9}, {%0,%1,%2,%3};"
        : "+r"(d[0]), "+r"(d[1]), "+r"(d[2]), "+r"(d[3])
        : "r"(a[0]), "r"(a[1]), "r"(a[2]), "r"(a[3]), "r"(b[0]), "r"(b[1]));
}
__device__ __forceinline__ int dp4a_(int a, int b, int c) {
    int d;
    asm("dp4a.s32.s32 %0, %1, %2, %3;" : "=r"(d) : "r"(a), "r"(b), "r"(c));
    return d;
}

// ---------------------------------------------------------------------------
// Once per replay: v = round(w*2^33) -> 4 balanced radix-256 digits, stored
// pre-swizzled in 32-row tile-contiguous layout. Rows: [W_res ; W_out ; 0].
// ---------------------------------------------------------------------------
__global__ __launch_bounds__(256) void split_w(const float* __restrict__ Wres,
                                               const float* __restrict__ Wout) {
    size_t i = (size_t)blockIdx.x * 256 + threadIdx.x;  // i = n*4096 + k over NROWS*NRES
    int n = (int)(i >> 12), k = (int)(i & 4095);
    float w = 0.0f;
    if (n < NRES)             w = Wres[i];
    else if (n < NRES + NCLS) w = Wout[(size_t)(n - NRES) * NRES + k];
    long long v = __double2ll_rn((double)w * SCALE);
    size_t tile  = ((size_t)(n >> 5) * KTILES + (k >> 7)) * ATILE_B;
    size_t inner = SWZ((uint32_t)((n & 31) * 128 + (k & 127)));
#pragma unroll
    for (int j = 0; j < NLIMB; j++) {
        long long d = ((v + 128) & 255) - 128;
        g_Lsw[j][tile + inner] = (int8_t)d;
        v = (v - d) >> 8;
    }
}

__global__ __launch_bounds__(256) void init_state(float* __restrict__ out) {
    int i = blockIdx.x * 256 + threadIdx.x;
    if (i < SSZ) g_S[0][i] = 0;                    // S(-1) = 0 (buffer 0)
    if (i < NRES * BATCH) g_vr[i] = 0.0f;
    if (i < BATCH * NCLS) {
        g_vc[i] = 0.0f;
        out[i]  = 0.0f;
    }
}

// no-op node: keeps the ncu-captured launch position on step_mma
__global__ void pad_kernel() {}

// ---------------------------------------------------------------------------
// step_mma (hybrid pipes, fused LIF):
//   warps 0-7 : IMMA path for limbs 1..3 (tensor pipe), per-limb accumulators,
//               exact fold tt += acc[li] << (8*li), li = 1..3.
//   warps 8-11: dp4a path for limb 0 (ALU/FMA pipe): lane = row (0..31),
//               warp-8 = 16-col group; int32 acc over full K; results -> sD0.
//   Epilogue (IMMA warps): total = sD0[n][b] + tt  -> exact int64, then LIF.
// Totals are bit-identical to the all-IMMA 4-limb version.
// ---------------------------------------------------------------------------
__global__ __launch_bounds__(THREADS, 1) void step_mma(const float* __restrict__ x,
                                                       const float* __restrict__ W_in,
                                                       float* __restrict__ out, int t) {
    extern __shared__ __align__(1024) char smem[];
    const uint32_t sbase = smem_u32(smem);
    const uint32_t mbar0 = sbase + SM_MBAR;
    int* __restrict__ sD0 = (int*)(smem + SM_D0);
    const int tid  = threadIdx.x;
    const int lane = tid & 31;
    const int warp = tid >> 5;
    const int mt   = blockIdx.x;         // 32-row tile, 0..128
    const int m0   = mt * MTILE;

    const int8_t* __restrict__ Ssrc = g_S[t & 1];
    int8_t* __restrict__       Sdst = g_S[(t + 1) & 1];

    if (tid == 0) {
#pragma unroll
        for (int s = 0; s < NSTAGE; s++) MBARRIER_INIT(mbar0 + 8 * s, 1);
    }
    __syncthreads();

    auto issue = [&](int c, int buf) {
        const int kt0 = c * 2;                       // first 128-k tile of chunk
        const uint32_t st = sbase + buf * SM_BUF;
        const uint32_t mb = mbar0 + 8 * buf;
        MBARRIER_EXPECT_TX(mb, SM_BUF);
#pragma unroll
        for (int li = 0; li < NLIMB; li++)
            bulk_cp(st + li * (2 * ATILE_B),
                    g_Lsw[li] + ((size_t)mt * KTILES + kt0) * ATILE_B,
                    2 * ATILE_B, mb);
        bulk_cp(st + SM_ABYTES, Ssrc + (size_t)kt0 * BTILE_B, 2 * BTILE_B, mb);
    };

    if (tid == 0) { issue(0, 0); issue(1, 1); issue(2, 2); }

    // ---- IMMA-warp state ----
    const int wm   = warp & 1;           // (warps 0-7) 0..1 (M, 16 rows)
    const int wn   = warp >> 1;          // 0..3 (N, 16 cols)
    long long tt[2][4];
#pragma unroll
    for (int ni = 0; ni < 2; ni++)
#pragma unroll
        for (int j = 0; j < 4; j++) tt[ni][j] = 0;
    const int arow  = wm * 16 + (lane & 15);
    const int acolx = (lane >> 4) << 4;
    const int brow  = wn * 16 + (lane & 7);
    const int bcolx = ((lane >> 3) & 1) << 4;

    // ---- dp4a-warp state ----
    const int dcg = warp - 8;            // (warps 8-11) col group: cols [dcg*16, +16)
    int dacc[16];
#pragma unroll
    for (int j = 0; j < 16; j++) dacc[j] = 0;

    int cbuf = 0, cpar = 0, pbuf = 0;

    for (int c = 0; c < NKCH; c++) {
        MBARRIER_WAIT_PARITY(mbar0 + 8 * cbuf, cpar);

        const uint32_t aoff = cbuf * SM_BUF;         // byte offset of chunk buffers
        const uint32_t boff = aoff + SM_ABYTES;

        if (warp < 8) {
            // ---- IMMA: limbs 1..3 on tensor pipe ----
            const uint32_t abase = sbase + aoff;
            const uint32_t bbase = sbase + boff;
            int acc[3][2][4];
#pragma unroll
            for (int li = 0; li < 3; li++)
#pragma unroll
                for (int ni = 0; ni < 2; ni++)
#pragma unroll
                    for (int j = 0; j < 4; j++) acc[li][ni][j] = 0;

#pragma unroll
            for (int kk = 0; kk < 8; kk++) {         // 8 x k32 per 256-k chunk
                const uint32_t asub0 = abase + (kk >> 2) * ATILE_B;
                const uint32_t bsub  = bbase + (kk >> 2) * BTILE_B;
                const int kko = (kk & 3) * 32;
                uint32_t b[2][2];
#pragma unroll
                for (int ni = 0; ni < 2; ni++)
                    ldmx2(b[ni], bsub + SWZ((brow + ni * 8) * 128 + kko + bcolx));
#pragma unroll
                for (int li = 0; li < 3; li++) {     // limb regions 1..3
                    uint32_t a[4];
                    ldmx4(a, asub0 + (li + 1) * (2 * ATILE_B) + SWZ(arow * 128 + kko + acolx));
#pragma unroll
                    for (int ni = 0; ni < 2; ni++)
                        imma16832(acc[li][ni], a, b[ni]);
                }
            }
#pragma unroll
            for (int li = 0; li < 3; li++)
#pragma unroll
                for (int ni = 0; ni < 2; ni++)
#pragma unroll
                    for (int j = 0; j < 4; j++)
                        tt[ni][j] += ((long long)acc[li][ni][j]) << (8 * (li + 1));
        } else {
            // ---- dp4a: limb 0 on ALU pipe. lane = row, dcg = col group. ----
#pragma unroll
            for (int k16 = 0; k16 < 16; k16++) {     // 16B k-groups over 256 k
                const uint32_t asub = aoff + (k16 >> 3) * ATILE_B;   // limb0 region
                const uint32_t bsub = boff + (k16 >> 3) * BTILE_B;
                const int ko = (k16 & 7) * 16;
                uint4 av = *(const uint4*)(smem + asub + SWZ((uint32_t)(lane * 128 + ko)));
#pragma unroll
                for (int j = 0; j < 16; j++) {
                    uint4 bv = *(const uint4*)(smem + bsub +
                                   SWZ((uint32_t)((dcg * 16 + j) * 128 + ko)));
                    dacc[j] = dp4a_((int)av.x, (int)bv.x, dacc[j]);
                    dacc[j] = dp4a_((int)av.y, (int)bv.y, dacc[j]);
                    dacc[j] = dp4a_((int)av.z, (int)bv.z, dacc[j]);
                    dacc[j] = dp4a_((int)av.w, (int)bv.w, dacc[j]);
                }
            }
        }

        __syncthreads();                             // buffer reuse + sD0 timing
        if (tid == 0 && c + 3 < NKCH) issue(c + 3, pbuf);
        if (++pbuf == NSTAGE) pbuf = 0;
        if (++cbuf == NSTAGE) { cbuf = 0; cpar ^= 1; }
    }

    // dp4a warps publish limb-0 totals
    if (warp >= 8) {
#pragma unroll
        for (int j = 0; j < 16; j++)
            sD0[lane * 64 + dcg * 16 + j] = dacc[j];
    }
    __syncthreads();

    // ---- fused LIF epilogue (IMMA warps own the cells) ----
    if (warp < 8) {
        const int g = lane >> 2, t4 = lane & 3;
#pragma unroll
        for (int ni = 0; ni < 2; ni++) {
#pragma unroll
            for (int h = 0; h < 2; h++) {            // row half: g, g+8
                int nloc = wm * 16 + g + h * 8;
                int n    = m0 + nloc;
#pragma unroll
                for (int q = 0; q < 2; q++) {        // col pair
                    int   b    = wn * 16 + ni * 8 + t4 * 2 + q;
                    long long T = tt[ni][h * 2 + q] + (long long)sD0[nloc * 64 + b];
                    float dotf = (float)((double)T * INVSCALE);
                    if (n < NRES) {
                        int   idx = n * BATCH + b;
                        float xw  = __fmul_rn(x[b * TSTEPS + t], W_in[n]);
                        float cur = __fadd_rn(xw, dotf);
                        float v   = __fadd_rn(__fmul_rn(0.9f, g_vr[idx]), cur);
                        float s   = (v >= 1.0f) ? 1.0f : 0.0f;
                        g_vr[idx] = v * (1.0f - s);
                        Sdst[(size_t)(n >> 7) * BTILE_B + SWZ((uint32_t)(b * 128 + (n & 127)))] = (int8_t)s;
                    } else if (n < NRES + NCLS) {    // classifier, step t-1
                        int   idx = b * NCLS + (n - NRES);
                        float v   = __fadd_rn(__fmul_rn(0.9f, g_vc[idx]), dotf);
                        float sc  = (v >= 1.0f) ? 1.0f : 0.0f;
                        g_vc[idx] = v * (1.0f - sc);
                        out[idx] += sc;
                    }
                }
            }
        }
    }
}

// ---------------------------------------------------------------------------
// final_readout: classifier update for the LAST step using S(T-1), fp64 dots.
// ---------------------------------------------------------------------------
__global__ __launch_bounds__(256) void final_readout(const float* __restrict__ W_out,
                                                     float* __restrict__ out) {
    __shared__ double red[8][NCLS];
    const int b = blockIdx.x, tid = threadIdx.x;
    const int k0 = tid * 16;

    float s[16];
    const int8_t* S = g_S[TSTEPS & 1] + (size_t)(k0 >> 7) * BTILE_B
                    + SWZ((uint32_t)(b * 128 + (k0 & 127)));
#pragma unroll
    for (int j = 0; j < 16; j++) s[j] = (float)S[j];

    double acc[NCLS];
#pragma unroll
    for (int c = 0; c < NCLS; c++) {
        const float* W = W_out + (size_t)c * NRES + k0;
        double a = 0.0;
#pragma unroll
        for (int j = 0; j < 16; j++) a += (double)s[j] * (double)W[j];
        acc[c] = a;
    }
#pragma unroll
    for (int c = 0; c < NCLS; c++)
#pragma unroll
        for (int o = 16; o > 0; o >>= 1)
            acc[c] += __shfl_down_sync(0xffffffff, acc[c], o);
    if ((tid & 31) == 0)
#pragma unroll
        for (int c = 0; c < NCLS; c++) red[tid >> 5][c] = acc[c];
    __syncthreads();

    if (tid < NCLS) {
        double dot = 0.0;
#pragma unroll
        for (int w = 0; w < 8; w++) dot += red[w][tid];
        int   idx = b * NCLS + tid;
        float v   = __fadd_rn(__fmul_rn(0.9f, g_vc[idx]), (float)dot);
        float sc  = (v >= 1.0f) ? 1.0f : 0.0f;
        g_vc[idx] = v * (1.0f - sc);
        out[idx] += sc;
    }
}

// ---------------------------------------------------------------------------
extern "C" void kernel_launch(void* const* d_in, const int* in_sizes, int n_in,
                              void* d_out, int out_size)
{
    const float* x     = (const float*)d_in[0];  // [64,1,128]
    const float* W_in  = (const float*)d_in[1];  // [4096,1]
    const float* W_res = (const float*)d_in[2];  // [4096,4096]
    const float* W_out = (const float*)d_in[3];  // [10,4096]
    float*       out   = (float*)d_out;          // [64,10]

    cudaFuncSetAttribute(step_mma, cudaFuncAttributeMaxDynamicSharedMemorySize, SM_TOTAL);

    split_w<<<((size_t)NROWS * NRES) / 256, 256>>>(W_res, W_out);
    init_state<<<(SSZ + 255) / 256, 256>>>(out);
    pad_kernel<<<1, 32>>>();

    for (int t = 0; t < TSTEPS; t++)
        step_mma<<<MTILES, THREADS, SM_TOTAL>>>(x, W_in, out, t);

    final_readout<<<BATCH, 256>>>(W_out, out);   // classifier step T-1 with S(T-1)
}

// round 17
// speedup vs baseline: 1.3122x; 1.1663x over previous
#include <cuda_runtime.h>
#include <cstdint>

#define BATCH  64
#define NRES   4096
#define NROWS  4128                     // 4096 reservoir + 10 classifier + 22 pad
#define TSTEPS 128
#define NCLS   10

#define MTILE  32
#define MTILES (NROWS / MTILE)          // 129
#define NLIMB  4
#define NKCH   16                       // k-chunks of 256 over K=4096
#define SCALE  8589934592.0             // 2^33 (proven exact-enough)
#define INVSCALE (1.0 / 8589934592.0)

#define KTILES  (NRES / 128)            // 32 global 128-k tiles
#define ATILE_B 4096                    // swizzled 32x128 s8 tile
#define BTILE_B 8192                    // swizzled 64x128 s8 tile
#define SSZ     (KTILES * BTILE_B)      // one spike buffer: 256 KB

#define NSTAGE   3
#define SM_ABYTES (NLIMB * 2 * ATILE_B) // 32768: 4 limbs x 2 k-tiles
#define SM_BUF    (SM_ABYTES + 2 * BTILE_B)  // 49152
#define SM_DATA   (NSTAGE * SM_BUF)          // 147456
#define SM_D0     SM_DATA                    // int32 sD0[2048] = 8192 B
#define SM_D1     (SM_DATA + 8192)           // int32 sD1[2048] = 8192 B
#define SM_MBAR   (SM_DATA + 16384)
#define SM_TOTAL  (SM_MBAR + 64)

#define THREADS 512   // warps 0-7: IMMA (limbs 2,3); warps 8-15: dp4a (limbs 0,1)

// ---------------- device scratch (no runtime allocation) ----------------
__device__ __align__(16384) int8_t g_Lsw[NLIMB][(size_t)NROWS * NRES];  // 32-row swizzled limb tiles
__device__ __align__(16384) int8_t g_S[2][SSZ];                         // spikes, double buffered
__device__ float g_vr[NRES * BATCH];    // [n][b]
__device__ float g_vc[BATCH * NCLS];

// ---------------- helpers ----------------
__device__ __forceinline__ uint32_t smem_u32(const void* p) {
    uint32_t a;
    asm("{ .reg .u64 t; cvta.to.shared.u64 t, %1; cvt.u32.u64 %0, t; }" : "=r"(a) : "l"(p));
    return a;
}
#define SWZ(off) ((off) ^ (((off) >> 3) & 0x70))

#define MBARRIER_INIT(mb, cnt) \
    asm volatile("mbarrier.init.shared.b64 [%0], %1;" :: "r"((uint32_t)(mb)), "r"((uint32_t)(cnt)) : "memory")
#define MBARRIER_EXPECT_TX(mb, bytes) \
    asm volatile("mbarrier.arrive.expect_tx.shared.b64 _, [%0], %1;" \
                 :: "r"((uint32_t)(mb)), "r"((uint32_t)(bytes)) : "memory")
#define MBARRIER_WAIT_PARITY(mb, par) do {                                   \
    uint32_t _m = (uint32_t)(mb), _p = (uint32_t)(par);                      \
    asm volatile(                                                            \
        "{\n\t.reg .pred P1;\n\t"                                            \
        "WL_%=:\n\t"                                                         \
        "mbarrier.try_wait.parity.acquire.cta.shared::cta.b64 P1, [%0], %1, 0x989680;\n\t" \
        "@P1 bra.uni WD_%=;\n\t"                                             \
        "bra.uni WL_%=;\n\t"                                                 \
        "WD_%=:\n\t}"                                                        \
        :: "r"(_m), "r"(_p) : "memory");                                     \
} while (0)

__device__ __forceinline__ void bulk_cp(uint32_t dst, const void* src, uint32_t bytes, uint32_t mbar) {
    asm volatile(
        "cp.async.bulk.shared::cluster.global.mbarrier::complete_tx::bytes [%0], [%1], %2, [%3];"
        :: "r"(dst), "l"(src), "r"(bytes), "r"(mbar) : "memory");
}
__device__ __forceinline__ void ldmx4(uint32_t* r, uint32_t a) {
    asm volatile("ldmatrix.sync.aligned.m8n8.x4.shared.b16 {%0,%1,%2,%3}, [%4];"
                 : "=r"(r[0]), "=r"(r[1]), "=r"(r[2]), "=r"(r[3]) : "r"(a));
}
__device__ __forceinline__ void ldmx2(uint32_t* r, uint32_t a) {
    asm volatile("ldmatrix.sync.aligned.m8n8.x2.shared.b16 {%0,%1}, [%2];"
                 : "=r"(r[0]), "=r"(r[1]) : "r"(a));
}
__device__ __forceinline__ void imma16832(int* d, const uint32_t* a, const uint32_t* b) {
    asm volatile(
        "mma.sync.aligned.m16n8k32.row.col.s32.s8.s8.s32 "
        "{%0,%1,%2,%3}, {%4,%5,%6,%7}, {%8,%9}, {%0,%1,%2,%3};"
        : "+r"(d[0]), "+r"(d[1]), "+r"(d[2]), "+r"(d[3])
        : "r"(a[0]), "r"(a[1]), "r"(a[2]), "r"(a[3]), "r"(b[0]), "r"(b[1]));
}
__device__ __forceinline__ int dp4a_(int a, int b, int c) {
    int d;
    asm("dp4a.s32.s32 %0, %1, %2, %3;" : "=r"(d) : "r"(a), "r"(b), "r"(c));
    return d;
}

// ---------------------------------------------------------------------------
// Once per replay: v = round(w*2^33) -> 4 balanced radix-256 digits, stored
// pre-swizzled in 32-row tile-contiguous layout. Rows: [W_res ; W_out ; 0].
// ---------------------------------------------------------------------------
__global__ __launch_bounds__(256) void split_w(const float* __restrict__ Wres,
                                               const float* __restrict__ Wout) {
    size_t i = (size_t)blockIdx.x * 256 + threadIdx.x;  // i = n*4096 + k over NROWS*NRES
    int n = (int)(i >> 12), k = (int)(i & 4095);
    float w = 0.0f;
    if (n < NRES)             w = Wres[i];
    else if (n < NRES + NCLS) w = Wout[(size_t)(n - NRES) * NRES + k];
    long long v = __double2ll_rn((double)w * SCALE);
    size_t tile  = ((size_t)(n >> 5) * KTILES + (k >> 7)) * ATILE_B;
    size_t inner = SWZ((uint32_t)((n & 31) * 128 + (k & 127)));
#pragma unroll
    for (int j = 0; j < NLIMB; j++) {
        long long d = ((v + 128) & 255) - 128;
        g_Lsw[j][tile + inner] = (int8_t)d;
        v = (v - d) >> 8;
    }
}

__global__ __launch_bounds__(256) void init_state(float* __restrict__ out) {
    int i = blockIdx.x * 256 + threadIdx.x;
    if (i < SSZ) g_S[0][i] = 0;                    // S(-1) = 0 (buffer 0)
    if (i < NRES * BATCH) g_vr[i] = 0.0f;
    if (i < BATCH * NCLS) {
        g_vc[i] = 0.0f;
        out[i]  = 0.0f;
    }
}

// no-op node: keeps the ncu-captured launch position on step_mma
__global__ void pad_kernel() {}

// ---------------------------------------------------------------------------
// step_mma (balanced hybrid pipes, fused LIF):
//   warps 0-7  : IMMA on limbs 2,3 (tensor pipe): 2 warps/SMSP x 32 IMMA/chunk
//                = 4096 cyc at rt~64.
//   warps 8-15 : dp4a on limbs 0,1 (fma/alu pipe): 2 warps/SMSP x 1024 dp4a
//                = 4096 cyc at rt~2. Exactly balanced with the IMMA side.
//   warp w in [8,16): limb = (w-8)&1, col group dcg = (w-8)>>1;
//   lane = row; results -> sD0/sD1 (int32, no write conflicts).
//   Epilogue: T = sD0 + (sD1<<8) + acc2<<16 + acc3<<24  (bit-identical).
// ---------------------------------------------------------------------------
__global__ __launch_bounds__(THREADS, 1) void step_mma(const float* __restrict__ x,
                                                       const float* __restrict__ W_in,
                                                       float* __restrict__ out, int t) {
    extern __shared__ __align__(1024) char smem[];
    const uint32_t sbase = smem_u32(smem);
    const uint32_t mbar0 = sbase + SM_MBAR;
    int* __restrict__ sD0 = (int*)(smem + SM_D0);
    int* __restrict__ sD1 = (int*)(smem + SM_D1);
    const int tid  = threadIdx.x;
    const int lane = tid & 31;
    const int warp = tid >> 5;
    const int mt   = blockIdx.x;         // 32-row tile, 0..128
    const int m0   = mt * MTILE;

    const int8_t* __restrict__ Ssrc = g_S[t & 1];
    int8_t* __restrict__       Sdst = g_S[(t + 1) & 1];

    if (tid == 0) {
#pragma unroll
        for (int s = 0; s < NSTAGE; s++) MBARRIER_INIT(mbar0 + 8 * s, 1);
    }
    __syncthreads();

    auto issue = [&](int c, int buf) {
        const int kt0 = c * 2;                       // first 128-k tile of chunk
        const uint32_t st = sbase + buf * SM_BUF;
        const uint32_t mb = mbar0 + 8 * buf;
        MBARRIER_EXPECT_TX(mb, SM_BUF);
#pragma unroll
        for (int li = 0; li < NLIMB; li++)
            bulk_cp(st + li * (2 * ATILE_B),
                    g_Lsw[li] + ((size_t)mt * KTILES + kt0) * ATILE_B,
                    2 * ATILE_B, mb);
        bulk_cp(st + SM_ABYTES, Ssrc + (size_t)kt0 * BTILE_B, 2 * BTILE_B, mb);
    };

    if (tid == 0) { issue(0, 0); issue(1, 1); issue(2, 2); }

    // ---- IMMA-warp state (warps 0-7) ----
    const int wm   = warp & 1;           // 0..1 (M, 16 rows)
    const int wn   = warp >> 1;          // 0..3 (N, 16 cols)
    long long tt[2][4];
#pragma unroll
    for (int ni = 0; ni < 2; ni++)
#pragma unroll
        for (int j = 0; j < 4; j++) tt[ni][j] = 0;
    const int arow  = wm * 16 + (lane & 15);
    const int acolx = (lane >> 4) << 4;
    const int brow  = wn * 16 + (lane & 7);
    const int bcolx = ((lane >> 3) & 1) << 4;

    // ---- dp4a-warp state (warps 8-15) ----
    const int dlimb = (warp - 8) & 1;    // limb 0 or 1
    const int dcg   = (warp - 8) >> 1;   // col group: cols [dcg*16, +16)
    int dacc[16];
#pragma unroll
    for (int j = 0; j < 16; j++) dacc[j] = 0;

    int cbuf = 0, cpar = 0, pbuf = 0;

    for (int c = 0; c < NKCH; c++) {
        MBARRIER_WAIT_PARITY(mbar0 + 8 * cbuf, cpar);

        const uint32_t aoff = cbuf * SM_BUF;
        const uint32_t boff = aoff + SM_ABYTES;

        if (warp < 8) {
            // ---- IMMA: limbs 2,3 on tensor pipe ----
            const uint32_t abase = sbase + aoff;
            const uint32_t bbase = sbase + boff;
            int acc[2][2][4];
#pragma unroll
            for (int li = 0; li < 2; li++)
#pragma unroll
                for (int ni = 0; ni < 2; ni++)
#pragma unroll
                    for (int j = 0; j < 4; j++) acc[li][ni][j] = 0;

#pragma unroll
            for (int kk = 0; kk < 8; kk++) {         // 8 x k32 per 256-k chunk
                const uint32_t asub0 = abase + (kk >> 2) * ATILE_B;
                const uint32_t bsub  = bbase + (kk >> 2) * BTILE_B;
                const int kko = (kk & 3) * 32;
                uint32_t b[2][2];
#pragma unroll
                for (int ni = 0; ni < 2; ni++)
                    ldmx2(b[ni], bsub + SWZ((brow + ni * 8) * 128 + kko + bcolx));
#pragma unroll
                for (int li = 0; li < 2; li++) {     // limb regions 2,3
                    uint32_t a[4];
                    ldmx4(a, asub0 + (li + 2) * (2 * ATILE_B) + SWZ(arow * 128 + kko + acolx));
#pragma unroll
                    for (int ni = 0; ni < 2; ni++)
                        imma16832(acc[li][ni], a, b[ni]);
                }
            }
#pragma unroll
            for (int li = 0; li < 2; li++)
#pragma unroll
                for (int ni = 0; ni < 2; ni++)
#pragma unroll
                    for (int j = 0; j < 4; j++)
                        tt[ni][j] += ((long long)acc[li][ni][j]) << (8 * (li + 2));
        } else {
            // ---- dp4a: limb dlimb on fma/alu pipe. lane = row, dcg = cols. ----
            const uint32_t areg = aoff + dlimb * (2 * ATILE_B);
#pragma unroll
            for (int k16 = 0; k16 < 16; k16++) {     // 16B k-groups over 256 k
                const uint32_t asub = areg + (k16 >> 3) * ATILE_B;
                const uint32_t bsub = boff + (k16 >> 3) * BTILE_B;
                const int ko = (k16 & 7) * 16;
                uint4 av = *(const uint4*)(smem + asub + SWZ((uint32_t)(lane * 128 + ko)));
#pragma unroll
                for (int j = 0; j < 16; j++) {
                    uint4 bv = *(const uint4*)(smem + bsub +
                                   SWZ((uint32_t)((dcg * 16 + j) * 128 + ko)));
                    dacc[j] = dp4a_((int)av.x, (int)bv.x, dacc[j]);
                    dacc[j] = dp4a_((int)av.y, (int)bv.y, dacc[j]);
                    dacc[j] = dp4a_((int)av.z, (int)bv.z, dacc[j]);
                    dacc[j] = dp4a_((int)av.w, (int)bv.w, dacc[j]);
                }
            }
        }

        __syncthreads();                             // buffer reuse safety
        if (tid == 0 && c + 3 < NKCH) issue(c + 3, pbuf);
        if (++pbuf == NSTAGE) pbuf = 0;
        if (++cbuf == NSTAGE) { cbuf = 0; cpar ^= 1; }
    }

    // dp4a warps publish limb totals (disjoint cells per warp)
    if (warp >= 8) {
        int* dst = dlimb ? sD1 : sD0;
#pragma unroll
        for (int j = 0; j < 16; j++)
            dst[lane * 64 + dcg * 16 + j] = dacc[j];
    }
    __syncthreads();

    // ---- fused LIF epilogue (IMMA warps own the cells) ----
    if (warp < 8) {
        const int g = lane >> 2, t4 = lane & 3;
#pragma unroll
        for (int ni = 0; ni < 2; ni++) {
#pragma unroll
            for (int h = 0; h < 2; h++) {            // row half: g, g+8
                int nloc = wm * 16 + g + h * 8;
                int n    = m0 + nloc;
#pragma unroll
                for (int q = 0; q < 2; q++) {        // col pair
                    int   b = wn * 16 + ni * 8 + t4 * 2 + q;
                    long long T = tt[ni][h * 2 + q]
                                + (long long)sD0[nloc * 64 + b]
                                + ((long long)sD1[nloc * 64 + b] << 8);
                    float dotf = (float)((double)T * INVSCALE);
                    if (n < NRES) {
                        int   idx = n * BATCH + b;
                        float xw  = __fmul_rn(x[b * TSTEPS + t], W_in[n]);
                        float cur = __fadd_rn(xw, dotf);
                        float v   = __fadd_rn(__fmul_rn(0.9f, g_vr[idx]), cur);
                        float s   = (v >= 1.0f) ? 1.0f : 0.0f;
                        g_vr[idx] = v * (1.0f - s);
                        Sdst[(size_t)(n >> 7) * BTILE_B + SWZ((uint32_t)(b * 128 + (n & 127)))] = (int8_t)s;
                    } else if (n < NRES + NCLS) {    // classifier, step t-1
                        int   idx = b * NCLS + (n - NRES);
                        float v   = __fadd_rn(__fmul_rn(0.9f, g_vc[idx]), dotf);
                        float sc  = (v >= 1.0f) ? 1.0f : 0.0f;
                        g_vc[idx] = v * (1.0f - sc);
                        out[idx] += sc;
                    }
                }
            }
        }
    }
}

// ---------------------------------------------------------------------------
// final_readout: classifier update for the LAST step using S(T-1), fp64 dots.
// ---------------------------------------------------------------------------
__global__ __launch_bounds__(256) void final_readout(const float* __restrict__ W_out,
                                                     float* __restrict__ out) {
    __shared__ double red[8][NCLS];
    const int b = blockIdx.x, tid = threadIdx.x;
    const int k0 = tid * 16;

    float s[16];
    const int8_t* S = g_S[TSTEPS & 1] + (size_t)(k0 >> 7) * BTILE_B
                    + SWZ((uint32_t)(b * 128 + (k0 & 127)));
#pragma unroll
    for (int j = 0; j < 16; j++) s[j] = (float)S[j];

    double acc[NCLS];
#pragma unroll
    for (int c = 0; c < NCLS; c++) {
        const float* W = W_out + (size_t)c * NRES + k0;
        double a = 0.0;
#pragma unroll
        for (int j = 0; j < 16; j++) a += (double)s[j] * (double)W[j];
        acc[c] = a;
    }
#pragma unroll
    for (int c = 0; c < NCLS; c++)
#pragma unroll
        for (int o = 16; o > 0; o >>= 1)
            acc[c] += __shfl_down_sync(0xffffffff, acc[c], o);
    if ((tid & 31) == 0)
#pragma unroll
        for (int c = 0; c < NCLS; c++) red[tid >> 5][c] = acc[c];
    __syncthreads();

    if (tid < NCLS) {
        double dot = 0.0;
#pragma unroll
        for (int w = 0; w < 8; w++) dot += red[w][tid];
        int   idx = b * NCLS + tid;
        float v   = __fadd_rn(__fmul_rn(0.9f, g_vc[idx]), (float)dot);
        float sc  = (v >= 1.0f) ? 1.0f : 0.0f;
        g_vc[idx] = v * (1.0f - sc);
        out[idx] += sc;
    }
}

// ---------------------------------------------------------------------------
extern "C" void kernel_launch(void* const* d_in, const int* in_sizes, int n_in,
                              void* d_out, int out_size)
{
    const float* x     = (const float*)d_in[0];  // [64,1,128]
    const float* W_in  = (const float*)d_in[1];  // [4096,1]
    const float* W_res = (const float*)d_in[2];  // [4096,4096]
    const float* W_out = (const float*)d_in[3];  // [10,4096]
    float*       out   = (float*)d_out;          // [64,10]

    cudaFuncSetAttribute(step_mma, cudaFuncAttributeMaxDynamicSharedMemorySize, SM_TOTAL);

    split_w<<<((size_t)NROWS * NRES) / 256, 256>>>(W_res, W_out);
    init_state<<<(SSZ + 255) / 256, 256>>>(out);
    pad_kernel<<<1, 32>>>();

    for (int t = 0; t < TSTEPS; t++)
        step_mma<<<MTILES, THREADS, SM_TOTAL>>>(x, W_in, out, t);

    final_readout<<<BATCH, 256>>>(W_out, out);   // classifier step T-1 with S(T-1)
}